// round 9
// baseline (speedup 1.0000x reference)
#include <cuda_runtime.h>
#include <math.h>
#include <stdint.h>

#define SQ   256
#define BBV  64
#define DIN  300
#define HHV  256
#define G4   1024
#define TT   34

typedef unsigned long long ull;

// ---------------- scratch ----------------
__device__ float g_xg_f[SQ * BBV * G4];     // [s][b][col]
__device__ float g_xg_b[SQ * BBV * G4];
__device__ float g_h_f [SQ * HHV * BBV];    // [s][u][b]
__device__ float g_h_b [SQ * HHV * BBV];
__device__ float g_emit[BBV * SQ * TT];     // [b][s][t]
__device__ float g_llh [BBV];
__device__ float g_dummy[32];

// ---------------- f32x2 / cluster helpers ----------------
__device__ __forceinline__ ull fma2(ull a, ull b, ull c) {
    ull d; asm("fma.rn.f32x2 %0, %1, %2, %3;" : "=l"(d) : "l"(a), "l"(b), "l"(c)); return d;
}
__device__ __forceinline__ ull add2(ull a, ull b) {
    ull d; asm("add.rn.f32x2 %0, %1, %2;" : "=l"(d) : "l"(a), "l"(b)); return d;
}
__device__ __forceinline__ ull pack2(float lo, float hi) {
    ull r; asm("mov.b64 %0, {%1, %2};" : "=l"(r) : "f"(lo), "f"(hi)); return r;
}
__device__ __forceinline__ float2 unpack2(ull v) {
    float2 r; asm("mov.b64 {%0, %1}, %2;" : "=f"(r.x), "=f"(r.y) : "l"(v)); return r;
}
__device__ __forceinline__ unsigned smem_u32(const void* p) {
    unsigned a;
    asm("{ .reg .u64 t; cvta.to.shared.u64 t, %1; cvt.u32.u64 %0, t; }" : "=r"(a) : "l"(p));
    return a;
}
__device__ __forceinline__ unsigned mapa_u32(unsigned a, unsigned r) {
    unsigned d; asm("mapa.shared::cluster.u32 %0, %1, %2;" : "=r"(d) : "r"(a), "r"(r)); return d;
}
__device__ __forceinline__ void st_cluster_f32(unsigned a, float v) {
    asm volatile("st.shared::cluster.f32 [%0], %1;" :: "r"(a), "f"(v) : "memory");
}
#define CLUSTER_SYNC() do { \
    asm volatile("barrier.cluster.arrive.aligned;" ::: "memory"); \
    asm volatile("barrier.cluster.wait.aligned;"   ::: "memory"); } while (0)

__device__ __forceinline__ float fsigmoid(float x) {
    return __fdividef(1.f, 1.f + __expf(-x));
}
__device__ __forceinline__ float ftanh(float x) {
    float e = __expf(2.f * x);
    return __fdividef(e - 1.f, e + 1.f);
}

// ============================================================================
// Kernel 1: embedding-gather + input projection SGEMM, f32x2.
// NEW structure (vs R8): A read from smem as natural adjacent-m f32x2 pairs
// (no smem duplication), B duplicated in REGISTERS (alu-pipe MOVs).
// LDS per thread per k: 64 B (was 96 B) for the same 32 fma2.
// acc2[i2][j] = rows (ty*8+2*i2, +1) x col (tx*8+j).
// ============================================================================
__global__ void __launch_bounds__(256) input_gemm(
    const float* __restrict__ emb, const int* __restrict__ batch,
    const float* __restrict__ wf, const float* __restrict__ bf,
    const float* __restrict__ wb, const float* __restrict__ bb)
{
    __shared__ __align__(16) float As[8 * 128];
    __shared__ __align__(16) float Bs[8 * 128];

    int tid = threadIdx.x;
    int bm  = blockIdx.y * 128;
    int bnG = blockIdx.x * 128;
    int dir = (bnG >= G4) ? 1 : 0;
    int j0  = bnG - dir * G4;
    const float* W    = dir ? wb : wf;
    const float* bias = dir ? bb : bf;
    float*       outp = dir ? g_xg_b : g_xg_f;

    int am = tid & 127;
    int ak = (tid >> 7) << 2;
    int mg = bm + am;
    int token = batch[(mg & 63) * SQ + (mg >> 6)];
    const float* arow = emb + (size_t)token * DIN;
    const float* wrow = W + (size_t)(j0 + am) * DIN;

    int tx = tid & 15, ty = tid >> 4;
    ull acc2[4][8];
#pragma unroll
    for (int i = 0; i < 4; ++i)
#pragma unroll
        for (int j = 0; j < 8; ++j) acc2[i][j] = 0ULL;

    for (int kk = 0; kk < DIN; kk += 8) {
        int k0 = kk + ak;
        float4 av, bv;
        if (k0 + 3 < DIN) {
            av = *(const float4*)(arow + k0);
            bv = *(const float4*)(wrow + k0);
        } else {
            av = make_float4(k0 < DIN ? arow[k0] : 0.f,
                             k0 + 1 < DIN ? arow[k0 + 1] : 0.f,
                             k0 + 2 < DIN ? arow[k0 + 2] : 0.f, 0.f);
            bv = make_float4(k0 < DIN ? wrow[k0] : 0.f,
                             k0 + 1 < DIN ? wrow[k0 + 1] : 0.f,
                             k0 + 2 < DIN ? wrow[k0 + 2] : 0.f, 0.f);
        }
        As[(ak + 0) * 128 + am] = av.x;
        As[(ak + 1) * 128 + am] = av.y;
        As[(ak + 2) * 128 + am] = av.z;
        As[(ak + 3) * 128 + am] = av.w;
        Bs[(ak + 0) * 128 + am] = bv.x;
        Bs[(ak + 1) * 128 + am] = bv.y;
        Bs[(ak + 2) * 128 + am] = bv.z;
        Bs[(ak + 3) * 128 + am] = bv.w;
        __syncthreads();
#pragma unroll
        for (int k = 0; k < 8; ++k) {
            const ulonglong2* ap = (const ulonglong2*)(As + k * 128 + ty * 8);
            ulonglong2 aA = ap[0], aB = ap[1];
            ull a[4] = {aA.x, aA.y, aB.x, aB.y};     // m-pairs, no dup needed
            const float4* bp = (const float4*)(Bs + k * 128 + tx * 8);
            float4 b0 = bp[0], b1 = bp[1];
            ull bd[8];
            bd[0] = pack2(b0.x, b0.x); bd[1] = pack2(b0.y, b0.y);
            bd[2] = pack2(b0.z, b0.z); bd[3] = pack2(b0.w, b0.w);
            bd[4] = pack2(b1.x, b1.x); bd[5] = pack2(b1.y, b1.y);
            bd[6] = pack2(b1.z, b1.z); bd[7] = pack2(b1.w, b1.w);
#pragma unroll
            for (int i = 0; i < 4; ++i)
#pragma unroll
                for (int j = 0; j < 8; ++j)
                    acc2[i][j] = fma2(a[i], bd[j], acc2[i][j]);
        }
        __syncthreads();
    }

    float bb8[8];
#pragma unroll
    for (int j = 0; j < 8; ++j) bb8[j] = bias[j0 + tx * 8 + j];
#pragma unroll
    for (int i2 = 0; i2 < 4; ++i2) {
        int m0 = bm + ty * 8 + 2 * i2;
        float* orow0 = outp + (size_t)m0 * G4 + j0 + tx * 8;
        float* orow1 = orow0 + G4;
#pragma unroll
        for (int j = 0; j < 8; ++j) {
            float2 p = unpack2(acc2[i2][j]);
            orow0[j] = p.x + bb8[j];
            orow1[j] = p.y + bb8[j];
        }
    }
}

// ============================================================================
__global__ void dummy_kernel(int v)
{
    g_dummy[threadIdx.x] = (float)v;
}

// ============================================================================
// Kernel 2: BiLSTM via 8-CTA clusters (identical to R7/R8).
// ============================================================================
__global__ void __cluster_dims__(8, 1, 1) __launch_bounds__(256) lstm_kernel(
    const float* __restrict__ whhf, const float* __restrict__ whhb)
{
    extern __shared__ __align__(16) float sm[];
    float* ws   = sm;                // [256 k][128 lc]   131072 B
    float* hs   = sm + 32768;        // [2][256 k][8 b]    16384 B
    float* gbuf = sm + 36864;        // [8 b][132]
    float* rbuf = gbuf + 1056;       // [128][8]

    int tid = threadIdx.x;
    int cid = blockIdx.x >> 3;
    int r   = blockIdx.x & 7;
    int dir = cid >> 3;
    int B0  = (cid & 7) * 8;
    const float* Whh = dir ? whhb : whhf;
    const float* xg  = dir ? g_xg_b : g_xg_f;
    float*       hh  = dir ? g_h_b  : g_h_f;

    for (int idx = tid; idx < 32768; idx += 256) {
        int lc = idx >> 8, k = idx & 255;
        int gcol = ((lc >> 5) << 8) + r * 32 + (lc & 31);
        ws[k * 128 + lc] = Whh[(size_t)gcol * 256 + k];
    }
    for (int i = tid; i < 512; i += 256)
        ((float4*)hs)[i] = make_float4(0.f, 0.f, 0.f, 0.f);
    __syncthreads();

    int ks = tid >> 7, r7 = tid & 127, bp = r7 & 3, cg = r7 >> 2;
    int lc = cg << 2;
    int gcol = ((lc >> 5) << 8) + r * 32 + (lc & 31);
    int cb = tid & 7, cu = tid >> 3;
    float creg = 0.f;

    unsigned hsa = smem_u32(hs);
    unsigned rb[8];
#pragma unroll
    for (int j = 0; j < 8; ++j) rb[j] = mapa_u32(hsa, (unsigned)j);

    for (int it = 0; it < 256; ++it) {
        int s = dir ? (255 - it) : it;
        int buf = it & 1, nbuf = buf ^ 1;

        float4 xv0, xv1;
        if (ks == 0) {
            const float* xb = xg + ((size_t)(s * 64 + B0 + 2 * bp)) * G4 + gcol;
            xv0 = *(const float4*)xb;
            xv1 = *(const float4*)(xb + G4);
        }

        ull a00 = 0, a01 = 0, a10 = 0, a11 = 0;
        const float* wp = ws + (ks * 128) * 128 + lc;
        const float* hp = hs + buf * 2048 + (ks * 128) * 8 + 2 * bp;
#pragma unroll 8
        for (int k = 0; k < 128; ++k) {
            ulonglong2 wv = *(const ulonglong2*)wp;
            float2 h2 = *(const float2*)hp;
            ull hd0 = pack2(h2.x, h2.x);
            ull hd1 = pack2(h2.y, h2.y);
            a00 = fma2(wv.x, hd0, a00);
            a01 = fma2(wv.y, hd0, a01);
            a10 = fma2(wv.x, hd1, a10);
            a11 = fma2(wv.y, hd1, a11);
            wp += 128; hp += 8;
        }

        if (ks == 1) {
            ulonglong2* rp = (ulonglong2*)(rbuf + r7 * 8);
            ulonglong2 v0; v0.x = a00; v0.y = a01;
            ulonglong2 v1; v1.x = a10; v1.y = a11;
            rp[0] = v0; rp[1] = v1;
        }
        __syncthreads();
        if (ks == 0) {
            const ulonglong2* rp = (const ulonglong2*)(rbuf + r7 * 8);
            ulonglong2 p0 = rp[0], p1 = rp[1];
            a00 = add2(a00, p0.x); a01 = add2(a01, p0.y);
            a10 = add2(a10, p1.x); a11 = add2(a11, p1.y);
            float2 c01 = unpack2(a00), c23 = unpack2(a01);
            float2 d01 = unpack2(a10), d23 = unpack2(a11);
            float* q0 = gbuf + (2 * bp) * 132 + lc;
            float* q1 = gbuf + (2 * bp + 1) * 132 + lc;
            q0[0] = c01.x + xv0.x; q0[1] = c01.y + xv0.y;
            q0[2] = c23.x + xv0.z; q0[3] = c23.y + xv0.w;
            q1[0] = d01.x + xv1.x; q1[1] = d01.y + xv1.y;
            q1[2] = d23.x + xv1.z; q1[3] = d23.y + xv1.w;
        }
        __syncthreads();

        {
            float iv = gbuf[cb * 132 +      cu];
            float fv = gbuf[cb * 132 + 32 + cu];
            float gv = gbuf[cb * 132 + 64 + cu];
            float ov = gbuf[cb * 132 + 96 + cu];
            float si = fsigmoid(iv);
            float sf = fsigmoid(fv);
            float so = fsigmoid(ov);
            creg = sf * creg + si * ftanh(gv);
            float hv = so * ftanh(creg);
            hh[(size_t)s * 16384 + (r * 32 + cu) * 64 + B0 + cb] = hv;

            if (it != 255) {
                unsigned off = (unsigned)(nbuf * 2048 + (r * 32 + cu) * 8 + cb) * 4u;
#pragma unroll
                for (int j = 0; j < 8; ++j) st_cluster_f32(rb[j] + off, hv);
            }
        }
        if (it != 255) CLUSTER_SYNC();
    }
}

// ============================================================================
// Kernel 3: emissions (identical to R8).
// ============================================================================
__global__ void __launch_bounds__(256) emis_kernel(
    const float* __restrict__ w_out, const float* __restrict__ b_out)
{
    extern __shared__ __align__(16) float hsm[];
    int s = blockIdx.x >> 1, half = blockIdx.x & 1;
    int tid = threadIdx.x;

    const float4* hf = (const float4*)(g_h_f + (size_t)s * 16384) + half * 8;
    const float4* hb = (const float4*)(g_h_b + (size_t)s * 16384) + half * 8;
    for (int f = tid; f < 2048; f += 256) {
        int u = f >> 3, q = f & 7;
        ((float4*)hsm)[u * 8 + q]        = hf[u * 16 + q];
        ((float4*)hsm)[2048 + u * 8 + q] = hb[u * 16 + q];
    }
    __syncthreads();

    for (int o = tid; o < TT * 32; o += 256) {
        int t = o >> 5, b = o & 31;
        const float4* wr = (const float4*)(w_out + (size_t)t * 512);
        float acc = 0.f;
#pragma unroll 4
        for (int u4 = 0; u4 < 128; ++u4) {
            float4 w = __ldg(wr + u4);
            acc += hsm[(u4 * 4 + 0) * 32 + b] * w.x
                 + hsm[(u4 * 4 + 1) * 32 + b] * w.y
                 + hsm[(u4 * 4 + 2) * 32 + b] * w.z
                 + hsm[(u4 * 4 + 3) * 32 + b] * w.w;
        }
        g_emit[((size_t)(half * 32 + b) * SQ + s) * TT + t] = acc + __ldg(b_out + t);
    }
}

// ============================================================================
// Kernel 4: CRF NLL (identical to R8).
// ============================================================================
__global__ void __launch_bounds__(64) crf_kernel(
    const int* __restrict__ tags,
    const float* __restrict__ start_t, const float* __restrict__ end_t,
    const float* __restrict__ trans)
{
    __shared__ float bufA[40], bufB[40];
    __shared__ float red[64];
    int b = blockIdx.x, tid = threadIdx.x;
    const float* em = g_emit + (size_t)b * SQ * TT;

    float trw[TT];
    float emv_nxt = 0.f;
    if (tid < TT) {
#pragma unroll
        for (int t = 0; t < TT; ++t) trw[t] = __ldg(&trans[t * TT + tid]);
        bufA[tid] = start_t[tid] + em[tid];
        emv_nxt = em[TT + tid];
    }
    __syncthreads();

    float* cur = bufA;
    float* nxt = bufB;
    for (int s = 1; s < SQ; ++s) {
        if (tid < TT) {
            float emv = emv_nxt;
            if (s + 1 < SQ) emv_nxt = em[(s + 1) * TT + tid];
            float C = cur[0];
            float s0 = 0.f, s1 = 0.f, s2 = 0.f, s3 = 0.f;
#pragma unroll
            for (int i = 0; i < 8; ++i) {
                s0 += __expf(cur[4 * i + 0] + trw[4 * i + 0] - C);
                s1 += __expf(cur[4 * i + 1] + trw[4 * i + 1] - C);
                s2 += __expf(cur[4 * i + 2] + trw[4 * i + 2] - C);
                s3 += __expf(cur[4 * i + 3] + trw[4 * i + 3] - C);
            }
            s0 += __expf(cur[32] + trw[32] - C);
            s1 += __expf(cur[33] + trw[33] - C);
            nxt[tid] = C + __logf((s0 + s1) + (s2 + s3)) + emv;
        }
        __syncthreads();
        float* t_ = cur; cur = nxt; nxt = t_;
    }

    const int* tb = tags + b * SQ;
    float np = 0.f;
    for (int s = tid; s < SQ; s += 64)     np += em[s * TT + tb[s]];
    for (int s = tid; s < SQ - 1; s += 64) np += __ldg(&trans[tb[s] * TT + tb[s + 1]]);
    red[tid] = np;
    __syncthreads();
    if (tid < 32) {
        float a = red[tid] + red[tid + 32];
#pragma unroll
        for (int o = 16; o > 0; o >>= 1) a += __shfl_xor_sync(0xffffffffu, a, o);
        if (tid == 0) {
            float C = cur[0];
            float sum = 0.f;
            for (int q = 0; q < TT; ++q) sum += __expf(cur[q] + end_t[q] - C);
            float den = C + __logf(sum);
            float num = a + start_t[tb[0]] + end_t[tb[SQ - 1]];
            g_llh[b] = num - den;
        }
    }
}

// ============================================================================
__global__ void __launch_bounds__(64) finalize_kernel(float* out)
{
    __shared__ float r[64];
    int t = threadIdx.x;
    r[t] = g_llh[t];
    __syncthreads();
    for (int o = 32; o > 0; o >>= 1) {
        if (t < o) r[t] += r[t + o];
        __syncthreads();
    }
    if (t == 0) out[0] = -r[0] / 64.f;
}

// ============================================================================
// MEASUREMENT + OPTIMIZATION ROUND:
//  - new (LDS-halved) input_gemm, duplicated so the copy lands at the
//    profiled slot 4 -> gives G' directly.
//  - lstm_kernel launched twice (idempotent) -> wallclock gives L:
//      dur = 2*G' + L + 2167   (2167 = R8 pipeline minus old gemm 677)
// ============================================================================
extern "C" void kernel_launch(void* const* d_in, const int* in_sizes, int n_in,
                              void* d_out, int out_size)
{
    const int*   batch   = (const int*)  d_in[0];
    const int*   tags    = (const int*)  d_in[1];
    const float* emb     = (const float*)d_in[3];
    const float* w_ih_f  = (const float*)d_in[4];
    const float* w_hh_f  = (const float*)d_in[5];
    const float* b_f     = (const float*)d_in[6];
    const float* w_ih_b  = (const float*)d_in[7];
    const float* w_hh_b  = (const float*)d_in[8];
    const float* b_b     = (const float*)d_in[9];
    const float* w_out   = (const float*)d_in[10];
    const float* b_out   = (const float*)d_in[11];
    const float* start_t = (const float*)d_in[12];
    const float* end_t   = (const float*)d_in[13];
    const float* trans   = (const float*)d_in[14];
    float* out = (float*)d_out;

    const int LSTM_SMEM = (32768 + 4096 + 1056 + 1024) * 4;  // 155776 B
    const int EMIS_SMEM = 512 * 32 * 4;                      // 65536 B
    cudaFuncSetAttribute(lstm_kernel, cudaFuncAttributeMaxDynamicSharedMemorySize, LSTM_SMEM);
    cudaFuncSetAttribute(emis_kernel, cudaFuncAttributeMaxDynamicSharedMemorySize, EMIS_SMEM);

    input_gemm<<<dim3(16, 128), 256>>>(emb, batch, w_ih_f, b_f, w_ih_b, b_b);  // slot 1
    dummy_kernel<<<1, 32>>>(1);                                                // slot 2
    dummy_kernel<<<1, 32>>>(2);                                                // slot 3
    input_gemm<<<dim3(16, 128), 256>>>(emb, batch, w_ih_f, b_f, w_ih_b, b_b);  // slot 4 <- profiled (G')
    lstm_kernel<<<128, 256, LSTM_SMEM>>>(w_hh_f, w_hh_b);                      // slot 5
    lstm_kernel<<<128, 256, LSTM_SMEM>>>(w_hh_f, w_hh_b);                      // slot 6 (ablation: +L)
    emis_kernel<<<512, 256, EMIS_SMEM>>>(w_out, b_out);                        // slot 7
    crf_kernel<<<64, 64>>>(tags, start_t, end_t, trans);                       // slot 8
    finalize_kernel<<<1, 64>>>(out);                                           // slot 9
}

// round 10
// speedup vs baseline: 2.2011x; 2.2011x over previous
#include <cuda_runtime.h>
#include <math.h>
#include <stdint.h>

#define SQ   256
#define BBV  64
#define DIN  300
#define HHV  256
#define G4   1024
#define TT   34

typedef unsigned long long ull;

// ---------------- scratch ----------------
__device__ float g_xg_f[SQ * BBV * G4];     // [s][b][col]
__device__ float g_xg_b[SQ * BBV * G4];
__device__ float g_h_f [SQ * HHV * BBV];    // [s][u][b]
__device__ float g_h_b [SQ * HHV * BBV];
__device__ float g_emit[BBV * SQ * TT];     // [b][s][t]
__device__ float g_llh [BBV];
__device__ float g_dummy[32];

// ---------------- f32x2 / cluster helpers ----------------
__device__ __forceinline__ ull fma2(ull a, ull b, ull c) {
    ull d; asm("fma.rn.f32x2 %0, %1, %2, %3;" : "=l"(d) : "l"(a), "l"(b), "l"(c)); return d;
}
__device__ __forceinline__ ull add2(ull a, ull b) {
    ull d; asm("add.rn.f32x2 %0, %1, %2;" : "=l"(d) : "l"(a), "l"(b)); return d;
}
__device__ __forceinline__ ull pack2(float lo, float hi) {
    ull r; asm("mov.b64 %0, {%1, %2};" : "=l"(r) : "f"(lo), "f"(hi)); return r;
}
__device__ __forceinline__ float2 unpack2(ull v) {
    float2 r; asm("mov.b64 {%0, %1}, %2;" : "=f"(r.x), "=f"(r.y) : "l"(v)); return r;
}
__device__ __forceinline__ unsigned smem_u32(const void* p) {
    unsigned a;
    asm("{ .reg .u64 t; cvta.to.shared.u64 t, %1; cvt.u32.u64 %0, t; }" : "=r"(a) : "l"(p));
    return a;
}
__device__ __forceinline__ unsigned mapa_u32(unsigned a, unsigned r) {
    unsigned d; asm("mapa.shared::cluster.u32 %0, %1, %2;" : "=r"(d) : "r"(a), "r"(r)); return d;
}
__device__ __forceinline__ void st_cluster_f32(unsigned a, float v) {
    asm volatile("st.shared::cluster.f32 [%0], %1;" :: "r"(a), "f"(v) : "memory");
}
#define CLUSTER_SYNC() do { \
    asm volatile("barrier.cluster.arrive.aligned;" ::: "memory"); \
    asm volatile("barrier.cluster.wait.aligned;"   ::: "memory"); } while (0)

__device__ __forceinline__ float fsigmoid(float x) {
    return __fdividef(1.f, 1.f + __expf(-x));
}
__device__ __forceinline__ float ftanh(float x) {
    float e = __expf(2.f * x);
    return __fdividef(e - 1.f, e + 1.f);
}

// ============================================================================
// Kernel 1: embedding-gather + input projection SGEMM (R9 version, 591us).
// ============================================================================
__global__ void __launch_bounds__(256) input_gemm(
    const float* __restrict__ emb, const int* __restrict__ batch,
    const float* __restrict__ wf, const float* __restrict__ bf,
    const float* __restrict__ wb, const float* __restrict__ bb)
{
    __shared__ __align__(16) float As[8 * 128];
    __shared__ __align__(16) float Bs[8 * 128];

    int tid = threadIdx.x;
    int bm  = blockIdx.y * 128;
    int bnG = blockIdx.x * 128;
    int dir = (bnG >= G4) ? 1 : 0;
    int j0  = bnG - dir * G4;
    const float* W    = dir ? wb : wf;
    const float* bias = dir ? bb : bf;
    float*       outp = dir ? g_xg_b : g_xg_f;

    int am = tid & 127;
    int ak = (tid >> 7) << 2;
    int mg = bm + am;
    int token = batch[(mg & 63) * SQ + (mg >> 6)];
    const float* arow = emb + (size_t)token * DIN;
    const float* wrow = W + (size_t)(j0 + am) * DIN;

    int tx = tid & 15, ty = tid >> 4;
    ull acc2[4][8];
#pragma unroll
    for (int i = 0; i < 4; ++i)
#pragma unroll
        for (int j = 0; j < 8; ++j) acc2[i][j] = 0ULL;

    for (int kk = 0; kk < DIN; kk += 8) {
        int k0 = kk + ak;
        float4 av, bv;
        if (k0 + 3 < DIN) {
            av = *(const float4*)(arow + k0);
            bv = *(const float4*)(wrow + k0);
        } else {
            av = make_float4(k0 < DIN ? arow[k0] : 0.f,
                             k0 + 1 < DIN ? arow[k0 + 1] : 0.f,
                             k0 + 2 < DIN ? arow[k0 + 2] : 0.f, 0.f);
            bv = make_float4(k0 < DIN ? wrow[k0] : 0.f,
                             k0 + 1 < DIN ? wrow[k0 + 1] : 0.f,
                             k0 + 2 < DIN ? wrow[k0 + 2] : 0.f, 0.f);
        }
        As[(ak + 0) * 128 + am] = av.x;
        As[(ak + 1) * 128 + am] = av.y;
        As[(ak + 2) * 128 + am] = av.z;
        As[(ak + 3) * 128 + am] = av.w;
        Bs[(ak + 0) * 128 + am] = bv.x;
        Bs[(ak + 1) * 128 + am] = bv.y;
        Bs[(ak + 2) * 128 + am] = bv.z;
        Bs[(ak + 3) * 128 + am] = bv.w;
        __syncthreads();
#pragma unroll
        for (int k = 0; k < 8; ++k) {
            const ulonglong2* ap = (const ulonglong2*)(As + k * 128 + ty * 8);
            ulonglong2 aA = ap[0], aB = ap[1];
            ull a[4] = {aA.x, aA.y, aB.x, aB.y};
            const float4* bp = (const float4*)(Bs + k * 128 + tx * 8);
            float4 b0 = bp[0], b1 = bp[1];
            ull bd[8];
            bd[0] = pack2(b0.x, b0.x); bd[1] = pack2(b0.y, b0.y);
            bd[2] = pack2(b0.z, b0.z); bd[3] = pack2(b0.w, b0.w);
            bd[4] = pack2(b1.x, b1.x); bd[5] = pack2(b1.y, b1.y);
            bd[6] = pack2(b1.z, b1.z); bd[7] = pack2(b1.w, b1.w);
#pragma unroll
            for (int i = 0; i < 4; ++i)
#pragma unroll
                for (int j = 0; j < 8; ++j)
                    acc2[i][j] = fma2(a[i], bd[j], acc2[i][j]);
        }
        __syncthreads();
    }

    float bb8[8];
#pragma unroll
    for (int j = 0; j < 8; ++j) bb8[j] = bias[j0 + tx * 8 + j];
#pragma unroll
    for (int i2 = 0; i2 < 4; ++i2) {
        int m0 = bm + ty * 8 + 2 * i2;
        float* orow0 = outp + (size_t)m0 * G4 + j0 + tx * 8;
        float* orow1 = orow0 + G4;
#pragma unroll
        for (int j = 0; j < 8; ++j) {
            float2 p = unpack2(acc2[i2][j]);
            orow0[j] = p.x + bb8[j];
            orow1[j] = p.y + bb8[j];
        }
    }
}

// ============================================================================
__global__ void dummy_kernel(int v)
{
    g_dummy[threadIdx.x] = (float)v;
}

// ============================================================================
// Kernel 2: BiLSTM, 8-CTA clusters — mma loop rewritten with explicit
// register double-buffering (8-deep chunk staging) + __launch_bounds__(256,1)
// so ptxas keeps ~140 regs and hides the 29-cyc LDS latency.
// ============================================================================
__global__ void __cluster_dims__(8, 1, 1) __launch_bounds__(256, 1) lstm_kernel(
    const float* __restrict__ whhf, const float* __restrict__ whhb)
{
    extern __shared__ __align__(16) float sm[];
    float* ws   = sm;                // [256 k][128 lc]   131072 B
    float* hs   = sm + 32768;        // [2][256 k][8 b]    16384 B
    float* gbuf = sm + 36864;        // [8 b][132]
    float* rbuf = gbuf + 1056;       // [128][8]

    int tid = threadIdx.x;
    int cid = blockIdx.x >> 3;
    int r   = blockIdx.x & 7;
    int dir = cid >> 3;
    int B0  = (cid & 7) * 8;
    const float* Whh = dir ? whhb : whhf;
    const float* xg  = dir ? g_xg_b : g_xg_f;
    float*       hh  = dir ? g_h_b  : g_h_f;

    for (int idx = tid; idx < 32768; idx += 256) {
        int lc = idx >> 8, k = idx & 255;
        int gcol = ((lc >> 5) << 8) + r * 32 + (lc & 31);
        ws[k * 128 + lc] = Whh[(size_t)gcol * 256 + k];
    }
    for (int i = tid; i < 512; i += 256)
        ((float4*)hs)[i] = make_float4(0.f, 0.f, 0.f, 0.f);
    __syncthreads();

    int ks = tid >> 7, r7 = tid & 127, bp = r7 & 3, cg = r7 >> 2;
    int lc = cg << 2;
    int gcol = ((lc >> 5) << 8) + r * 32 + (lc & 31);
    int cb = tid & 7, cu = tid >> 3;
    float creg = 0.f;

    unsigned hsa = smem_u32(hs);
    unsigned rb[8];
#pragma unroll
    for (int j = 0; j < 8; ++j) rb[j] = mapa_u32(hsa, (unsigned)j);

    // fixed base pointers for this thread's k-slice
    const ulonglong2* wq = (const ulonglong2*)(ws + ks * 16384 + lc);  // [kk]*32
    const float2*     hq0 = (const float2*)(hs + ks * 1024 + 2 * bp); // [kk]*4 (+buf*1024 f2)

    for (int it = 0; it < 256; ++it) {
        int s = dir ? (255 - it) : it;
        int buf = it & 1, nbuf = buf ^ 1;

        float4 xv0, xv1;
        if (ks == 0) {
            const float* xb = xg + ((size_t)(s * 64 + B0 + 2 * bp)) * G4 + gcol;
            xv0 = *(const float4*)xb;
            xv1 = *(const float4*)(xb + G4);
        }

        ull a00 = 0, a01 = 0, a10 = 0, a11 = 0;
        const float2* hq = hq0 + buf * 1024;

        // ---- register double-buffered mma: 16 chunks of 8 k ----
        ulonglong2 wbuf[8]; float2 hbuf[8];
#pragma unroll
        for (int j = 0; j < 8; ++j) { wbuf[j] = wq[j * 32]; hbuf[j] = hq[j * 4]; }
        for (int c = 0; c < 16; ++c) {
            ulonglong2 wn[8]; float2 hn[8];
            if (c < 15) {
                int base = (c + 1) * 8;
#pragma unroll
                for (int j = 0; j < 8; ++j) {
                    wn[j] = wq[(base + j) * 32];
                    hn[j] = hq[(base + j) * 4];
                }
            }
#pragma unroll
            for (int j = 0; j < 8; ++j) {
                ull hd0 = pack2(hbuf[j].x, hbuf[j].x);
                ull hd1 = pack2(hbuf[j].y, hbuf[j].y);
                a00 = fma2(wbuf[j].x, hd0, a00);
                a01 = fma2(wbuf[j].y, hd0, a01);
                a10 = fma2(wbuf[j].x, hd1, a10);
                a11 = fma2(wbuf[j].y, hd1, a11);
            }
#pragma unroll
            for (int j = 0; j < 8; ++j) { wbuf[j] = wn[j]; hbuf[j] = hn[j]; }
        }

        if (ks == 1) {
            ulonglong2* rp = (ulonglong2*)(rbuf + r7 * 8);
            ulonglong2 v0; v0.x = a00; v0.y = a01;
            ulonglong2 v1; v1.x = a10; v1.y = a11;
            rp[0] = v0; rp[1] = v1;
        }
        __syncthreads();
        if (ks == 0) {
            const ulonglong2* rp = (const ulonglong2*)(rbuf + r7 * 8);
            ulonglong2 p0 = rp[0], p1 = rp[1];
            a00 = add2(a00, p0.x); a01 = add2(a01, p0.y);
            a10 = add2(a10, p1.x); a11 = add2(a11, p1.y);
            float2 c01 = unpack2(a00), c23 = unpack2(a01);
            float2 d01 = unpack2(a10), d23 = unpack2(a11);
            float* q0 = gbuf + (2 * bp) * 132 + lc;
            float* q1 = gbuf + (2 * bp + 1) * 132 + lc;
            q0[0] = c01.x + xv0.x; q0[1] = c01.y + xv0.y;
            q0[2] = c23.x + xv0.z; q0[3] = c23.y + xv0.w;
            q1[0] = d01.x + xv1.x; q1[1] = d01.y + xv1.y;
            q1[2] = d23.x + xv1.z; q1[3] = d23.y + xv1.w;
        }
        __syncthreads();

        {
            float iv = gbuf[cb * 132 +      cu];
            float fv = gbuf[cb * 132 + 32 + cu];
            float gv = gbuf[cb * 132 + 64 + cu];
            float ov = gbuf[cb * 132 + 96 + cu];
            float si = fsigmoid(iv);
            float sf = fsigmoid(fv);
            float so = fsigmoid(ov);
            creg = sf * creg + si * ftanh(gv);
            float hv = so * ftanh(creg);
            hh[(size_t)s * 16384 + (r * 32 + cu) * 64 + B0 + cb] = hv;

            if (it != 255) {
                unsigned off = (unsigned)(nbuf * 2048 + (r * 32 + cu) * 8 + cb) * 4u;
#pragma unroll
                for (int j = 0; j < 8; ++j) st_cluster_f32(rb[j] + off, hv);
            }
        }
        if (it != 255) CLUSTER_SYNC();
    }
}

// ============================================================================
// Kernel 3: emissions (unchanged).
// ============================================================================
__global__ void __launch_bounds__(256) emis_kernel(
    const float* __restrict__ w_out, const float* __restrict__ b_out)
{
    extern __shared__ __align__(16) float hsm[];
    int s = blockIdx.x >> 1, half = blockIdx.x & 1;
    int tid = threadIdx.x;

    const float4* hf = (const float4*)(g_h_f + (size_t)s * 16384) + half * 8;
    const float4* hb = (const float4*)(g_h_b + (size_t)s * 16384) + half * 8;
    for (int f = tid; f < 2048; f += 256) {
        int u = f >> 3, q = f & 7;
        ((float4*)hsm)[u * 8 + q]        = hf[u * 16 + q];
        ((float4*)hsm)[2048 + u * 8 + q] = hb[u * 16 + q];
    }
    __syncthreads();

    for (int o = tid; o < TT * 32; o += 256) {
        int t = o >> 5, b = o & 31;
        const float4* wr = (const float4*)(w_out + (size_t)t * 512);
        float acc = 0.f;
#pragma unroll 4
        for (int u4 = 0; u4 < 128; ++u4) {
            float4 w = __ldg(wr + u4);
            acc += hsm[(u4 * 4 + 0) * 32 + b] * w.x
                 + hsm[(u4 * 4 + 1) * 32 + b] * w.y
                 + hsm[(u4 * 4 + 2) * 32 + b] * w.z
                 + hsm[(u4 * 4 + 3) * 32 + b] * w.w;
        }
        g_emit[((size_t)(half * 32 + b) * SQ + s) * TT + t] = acc + __ldg(b_out + t);
    }
}

// ============================================================================
// Kernel 4: CRF NLL (unchanged).
// ============================================================================
__global__ void __launch_bounds__(64) crf_kernel(
    const int* __restrict__ tags,
    const float* __restrict__ start_t, const float* __restrict__ end_t,
    const float* __restrict__ trans)
{
    __shared__ float bufA[40], bufB[40];
    __shared__ float red[64];
    int b = blockIdx.x, tid = threadIdx.x;
    const float* em = g_emit + (size_t)b * SQ * TT;

    float trw[TT];
    float emv_nxt = 0.f;
    if (tid < TT) {
#pragma unroll
        for (int t = 0; t < TT; ++t) trw[t] = __ldg(&trans[t * TT + tid]);
        bufA[tid] = start_t[tid] + em[tid];
        emv_nxt = em[TT + tid];
    }
    __syncthreads();

    float* cur = bufA;
    float* nxt = bufB;
    for (int s = 1; s < SQ; ++s) {
        if (tid < TT) {
            float emv = emv_nxt;
            if (s + 1 < SQ) emv_nxt = em[(s + 1) * TT + tid];
            float C = cur[0];
            float s0 = 0.f, s1 = 0.f, s2 = 0.f, s3 = 0.f;
#pragma unroll
            for (int i = 0; i < 8; ++i) {
                s0 += __expf(cur[4 * i + 0] + trw[4 * i + 0] - C);
                s1 += __expf(cur[4 * i + 1] + trw[4 * i + 1] - C);
                s2 += __expf(cur[4 * i + 2] + trw[4 * i + 2] - C);
                s3 += __expf(cur[4 * i + 3] + trw[4 * i + 3] - C);
            }
            s0 += __expf(cur[32] + trw[32] - C);
            s1 += __expf(cur[33] + trw[33] - C);
            nxt[tid] = C + __logf((s0 + s1) + (s2 + s3)) + emv;
        }
        __syncthreads();
        float* t_ = cur; cur = nxt; nxt = t_;
    }

    const int* tb = tags + b * SQ;
    float np = 0.f;
    for (int s = tid; s < SQ; s += 64)     np += em[s * TT + tb[s]];
    for (int s = tid; s < SQ - 1; s += 64) np += __ldg(&trans[tb[s] * TT + tb[s + 1]]);
    red[tid] = np;
    __syncthreads();
    if (tid < 32) {
        float a = red[tid] + red[tid + 32];
#pragma unroll
        for (int o = 16; o > 0; o >>= 1) a += __shfl_xor_sync(0xffffffffu, a, o);
        if (tid == 0) {
            float C = cur[0];
            float sum = 0.f;
            for (int q = 0; q < TT; ++q) sum += __expf(cur[q] + end_t[q] - C);
            float den = C + __logf(sum);
            float num = a + start_t[tb[0]] + end_t[tb[SQ - 1]];
            g_llh[b] = num - den;
        }
    }
}

// ============================================================================
__global__ void __launch_bounds__(64) finalize_kernel(float* out)
{
    __shared__ float r[64];
    int t = threadIdx.x;
    r[t] = g_llh[t];
    __syncthreads();
    for (int o = 32; o > 0; o >>= 1) {
        if (t < o) r[t] += r[t + o];
        __syncthreads();
    }
    if (t == 0) out[0] = -r[0] / 64.f;
}

// ============================================================================
// Single launch of each kernel (going for the record). Dummies keep
// lstm_kernel at slot 4 = the ncu-profiled slot, to verify regs/issue%.
// ============================================================================
extern "C" void kernel_launch(void* const* d_in, const int* in_sizes, int n_in,
                              void* d_out, int out_size)
{
    const int*   batch   = (const int*)  d_in[0];
    const int*   tags    = (const int*)  d_in[1];
    const float* emb     = (const float*)d_in[3];
    const float* w_ih_f  = (const float*)d_in[4];
    const float* w_hh_f  = (const float*)d_in[5];
    const float* b_f     = (const float*)d_in[6];
    const float* w_ih_b  = (const float*)d_in[7];
    const float* w_hh_b  = (const float*)d_in[8];
    const float* b_b     = (const float*)d_in[9];
    const float* w_out   = (const float*)d_in[10];
    const float* b_out   = (const float*)d_in[11];
    const float* start_t = (const float*)d_in[12];
    const float* end_t   = (const float*)d_in[13];
    const float* trans   = (const float*)d_in[14];
    float* out = (float*)d_out;

    const int LSTM_SMEM = (32768 + 4096 + 1056 + 1024) * 4;  // 155776 B
    const int EMIS_SMEM = 512 * 32 * 4;                      // 65536 B
    cudaFuncSetAttribute(lstm_kernel, cudaFuncAttributeMaxDynamicSharedMemorySize, LSTM_SMEM);
    cudaFuncSetAttribute(emis_kernel, cudaFuncAttributeMaxDynamicSharedMemorySize, EMIS_SMEM);

    input_gemm<<<dim3(16, 128), 256>>>(emb, batch, w_ih_f, b_f, w_ih_b, b_b);  // slot 1
    dummy_kernel<<<1, 32>>>(1);                                                // slot 2
    dummy_kernel<<<1, 32>>>(2);                                                // slot 3
    lstm_kernel<<<128, 256, LSTM_SMEM>>>(w_hh_f, w_hh_b);                      // slot 4 <- profiled
    emis_kernel<<<512, 256, EMIS_SMEM>>>(w_out, b_out);                        // slot 5
    crf_kernel<<<64, 64>>>(tags, start_t, end_t, trans);                       // slot 6
    finalize_kernel<<<1, 64>>>(out);                                           // slot 7
}